// round 1
// baseline (speedup 1.0000x reference)
#include <cuda_runtime.h>
#include <math.h>

#define NB 8
#define NT 2048
#define NC 512
#define NK 512
#define SCALE 0.044194173824159216f  // 1/sqrt(512)

// Scratch (device globals: allocation-free per harness rules)
static __device__ float g_q[(size_t)NB * NT * NK];
static __device__ float g_k[(size_t)NB * NT * NK];
static __device__ float g_v[(size_t)NB * NT * NK];
static __device__ float g_S[(size_t)NB * NT * NT];
static __device__ float g_m[NB * NT];
static __device__ float g_iz[NB * NT];

// ---------------------------------------------------------------------------
// Kernel 1: q/k/v = x @ W^T + b   (NT GEMM, M=16384, N=512, K=512)
// 128x128 tile, BK=16, 8x8 per thread, 256 threads.
// blockIdx.z selects which of q/k/v.
// ---------------------------------------------------------------------------
__global__ void __launch_bounds__(256) qkv_kernel(
    const float* __restrict__ x,
    const float* __restrict__ Wq, const float* __restrict__ bq,
    const float* __restrict__ Wk, const float* __restrict__ bk,
    const float* __restrict__ Wv, const float* __restrict__ bv)
{
    const int which = blockIdx.z;
    const float* W    = (which == 0) ? Wq : (which == 1) ? Wk : Wv;
    const float* bias = (which == 0) ? bq : (which == 1) ? bk : bv;
    float* out        = (which == 0) ? g_q : (which == 1) ? g_k : g_v;

    const int m0 = blockIdx.y * 128;
    const int n0 = blockIdx.x * 128;

    __shared__ float As[16][128];
    __shared__ float Bs[16][128];

    const int tid = threadIdx.x;
    const int tx = tid % 16;
    const int ty = tid / 16;
    const int f0 = tid * 2;

    float acc[8][8] = {};

    for (int k0 = 0; k0 < NC; k0 += 16) {
        #pragma unroll
        for (int i = 0; i < 2; i++) {
            int f = f0 + i;
            int row = f >> 2;
            int k4 = (f & 3) * 4;
            float4 a = *(const float4*)(x + (size_t)(m0 + row) * NC + k0 + k4);
            As[k4 + 0][row] = a.x; As[k4 + 1][row] = a.y;
            As[k4 + 2][row] = a.z; As[k4 + 3][row] = a.w;
            float4 bv4 = *(const float4*)(W + (size_t)(n0 + row) * NC + k0 + k4);
            Bs[k4 + 0][row] = bv4.x; Bs[k4 + 1][row] = bv4.y;
            Bs[k4 + 2][row] = bv4.z; Bs[k4 + 3][row] = bv4.w;
        }
        __syncthreads();
        #pragma unroll
        for (int kk = 0; kk < 16; kk++) {
            float ra[8], rb[8];
            #pragma unroll
            for (int i = 0; i < 8; i++) ra[i] = As[kk][ty * 8 + i];
            #pragma unroll
            for (int j = 0; j < 8; j++) rb[j] = Bs[kk][tx * 8 + j];
            #pragma unroll
            for (int i = 0; i < 8; i++)
                #pragma unroll
                for (int j = 0; j < 8; j++)
                    acc[i][j] += ra[i] * rb[j];
        }
        __syncthreads();
    }

    #pragma unroll
    for (int i = 0; i < 8; i++) {
        int m = m0 + ty * 8 + i;
        #pragma unroll
        for (int j = 0; j < 8; j += 4) {
            int n = n0 + tx * 8 + j;
            float4 o;
            o.x = acc[i][j + 0] + bias[n + 0];
            o.y = acc[i][j + 1] + bias[n + 1];
            o.z = acc[i][j + 2] + bias[n + 2];
            o.w = acc[i][j + 3] + bias[n + 3];
            *(float4*)(out + (size_t)m * NK + n) = o;
        }
    }
}

// ---------------------------------------------------------------------------
// Kernel 2: S = (q @ k^T) * SCALE, lower-triangle tiles only (per batch)
// ---------------------------------------------------------------------------
__global__ void __launch_bounds__(256) scores_kernel()
{
    const int b  = blockIdx.z;
    const int qt = blockIdx.y;
    const int st = blockIdx.x;
    if (st > qt) return;  // strictly-upper tiles never read

    const float* A = g_q + (size_t)b * NT * NK;
    const float* Bm = g_k + (size_t)b * NT * NK;
    float* S = g_S + (size_t)b * NT * NT;

    const int m0 = qt * 128;
    const int n0 = st * 128;

    __shared__ float As[16][128];
    __shared__ float Bs[16][128];

    const int tid = threadIdx.x;
    const int tx = tid % 16;
    const int ty = tid / 16;
    const int f0 = tid * 2;

    float acc[8][8] = {};

    for (int k0 = 0; k0 < NK; k0 += 16) {
        #pragma unroll
        for (int i = 0; i < 2; i++) {
            int f = f0 + i;
            int row = f >> 2;
            int k4 = (f & 3) * 4;
            float4 a = *(const float4*)(A + (size_t)(m0 + row) * NK + k0 + k4);
            As[k4 + 0][row] = a.x; As[k4 + 1][row] = a.y;
            As[k4 + 2][row] = a.z; As[k4 + 3][row] = a.w;
            float4 bb = *(const float4*)(Bm + (size_t)(n0 + row) * NK + k0 + k4);
            Bs[k4 + 0][row] = bb.x; Bs[k4 + 1][row] = bb.y;
            Bs[k4 + 2][row] = bb.z; Bs[k4 + 3][row] = bb.w;
        }
        __syncthreads();
        #pragma unroll
        for (int kk = 0; kk < 16; kk++) {
            float ra[8], rb[8];
            #pragma unroll
            for (int i = 0; i < 8; i++) ra[i] = As[kk][ty * 8 + i];
            #pragma unroll
            for (int j = 0; j < 8; j++) rb[j] = Bs[kk][tx * 8 + j];
            #pragma unroll
            for (int i = 0; i < 8; i++)
                #pragma unroll
                for (int j = 0; j < 8; j++)
                    acc[i][j] += ra[i] * rb[j];
        }
        __syncthreads();
    }

    #pragma unroll
    for (int i = 0; i < 8; i++) {
        int m = m0 + ty * 8 + i;
        #pragma unroll
        for (int j = 0; j < 8; j += 4) {
            int n = n0 + tx * 8 + j;
            float4 o;
            o.x = acc[i][j + 0] * SCALE;
            o.y = acc[i][j + 1] * SCALE;
            o.z = acc[i][j + 2] * SCALE;
            o.w = acc[i][j + 3] * SCALE;
            *(float4*)(S + (size_t)m * NT + n) = o;
        }
    }
}

// ---------------------------------------------------------------------------
// Kernel 3: per-column (key-axis) softmax stats over the QUERY axis.
// For column s: m_s = max_{q>=s} S[q,s];  Z_s = sum_{q>=s} exp(S[q,s]-m_s).
// Block: 32 columns x 8 row-lanes, 256 threads.
// ---------------------------------------------------------------------------
__global__ void __launch_bounds__(256) colstats_kernel()
{
    const int b = blockIdx.y;
    const int c = threadIdx.x & 31;
    const int rl = threadIdx.x >> 5;     // 0..7
    const int col = blockIdx.x * 32 + c;
    const float* S = g_S + (size_t)b * NT * NT;

    __shared__ float red[8][32];

    const int qstart = (col & ~7) + rl;

    float m = -INFINITY;
    for (int q = qstart; q < NT; q += 8)
        if (q >= col) m = fmaxf(m, S[(size_t)q * NT + col]);

    red[rl][c] = m;
    __syncthreads();
    if (rl == 0) {
        #pragma unroll
        for (int r = 1; r < 8; r++) m = fmaxf(m, red[r][c]);
        red[0][c] = m;
    }
    __syncthreads();
    const float cm = red[0][c];
    __syncthreads();

    float z = 0.f;
    for (int q = qstart; q < NT; q += 8)
        if (q >= col) z += __expf(S[(size_t)q * NT + col] - cm);

    red[rl][c] = z;
    __syncthreads();
    if (rl == 0) {
        #pragma unroll
        for (int r = 1; r < 8; r++) z += red[r][c];
        g_m[b * NT + col] = cm;
        g_iz[b * NT + col] = 1.f / z;
    }
}

// ---------------------------------------------------------------------------
// Kernel 4: attn = P @ V with P[q,s] = (s<=q) ? exp(S[q,s]-m_s)*invZ_s : 0
// NN GEMM per batch; triangular k-range (s < q_tile_end).
// Writes attn into out[..., 512:1024].
// ---------------------------------------------------------------------------
__global__ void __launch_bounds__(256) attnv_kernel(float* __restrict__ out)
{
    const int b  = blockIdx.z;
    const int qt = blockIdx.y;
    const int n0 = blockIdx.x * 128;

    const float* S  = g_S + (size_t)b * NT * NT;
    const float* V  = g_v + (size_t)b * NT * NK;
    const float* cm = g_m + b * NT;
    const float* ciz = g_iz + b * NT;

    const int m0 = qt * 128;
    const int kend = m0 + 128;   // need s <= q <= m0+127

    __shared__ float As[16][128];   // [s][q] = P values (transposed)
    __shared__ float Bs[16][128];   // [s][n]

    const int tid = threadIdx.x;
    const int tx = tid % 16;
    const int ty = tid / 16;
    const int f0 = tid * 2;

    float acc[8][8] = {};

    for (int k0 = 0; k0 < kend; k0 += 16) {
        #pragma unroll
        for (int i = 0; i < 2; i++) {
            int f = f0 + i;
            // A tile: 128 q-rows x 16 s-cols
            {
                int row = f >> 2;
                int k4 = (f & 3) * 4;
                int q = m0 + row;
                int s = k0 + k4;
                float4 sv = *(const float4*)(S + (size_t)q * NT + s);
                As[k4 + 0][row] = (s + 0 <= q) ? __expf(sv.x - cm[s + 0]) * ciz[s + 0] : 0.f;
                As[k4 + 1][row] = (s + 1 <= q) ? __expf(sv.y - cm[s + 1]) * ciz[s + 1] : 0.f;
                As[k4 + 2][row] = (s + 2 <= q) ? __expf(sv.z - cm[s + 2]) * ciz[s + 2] : 0.f;
                As[k4 + 3][row] = (s + 3 <= q) ? __expf(sv.w - cm[s + 3]) * ciz[s + 3] : 0.f;
            }
            // B tile: 16 s-rows x 128 n-cols (direct layout)
            {
                int r = f >> 5;
                int c4 = (f & 31) * 4;
                float4 vv = *(const float4*)(V + (size_t)(k0 + r) * NK + n0 + c4);
                *(float4*)&Bs[r][c4] = vv;
            }
        }
        __syncthreads();
        #pragma unroll
        for (int kk = 0; kk < 16; kk++) {
            float ra[8], rb[8];
            #pragma unroll
            for (int i = 0; i < 8; i++) ra[i] = As[kk][ty * 8 + i];
            #pragma unroll
            for (int j = 0; j < 8; j++) rb[j] = Bs[kk][tx * 8 + j];
            #pragma unroll
            for (int i = 0; i < 8; i++)
                #pragma unroll
                for (int j = 0; j < 8; j++)
                    acc[i][j] += ra[i] * rb[j];
        }
        __syncthreads();
    }

    #pragma unroll
    for (int i = 0; i < 8; i++) {
        int q = m0 + ty * 8 + i;
        #pragma unroll
        for (int j = 0; j < 8; j += 4) {
            int n = n0 + tx * 8 + j;
            float4 o;
            o.x = acc[i][j + 0];
            o.y = acc[i][j + 1];
            o.z = acc[i][j + 2];
            o.w = acc[i][j + 3];
            *(float4*)(out + ((size_t)b * NT + q) * 1024 + 512 + n) = o;
        }
    }
}

// ---------------------------------------------------------------------------
// Kernel 5: out[..., 0:512] = x
// ---------------------------------------------------------------------------
__global__ void __launch_bounds__(256) copyx_kernel(
    const float* __restrict__ x, float* __restrict__ out)
{
    size_t idx4 = (size_t)blockIdx.x * blockDim.x + threadIdx.x;
    // total float4 = 8*2048*512/4 = 2,097,152
    size_t row = idx4 / 128;      // 128 float4 per 512-float x row
    size_t c4  = idx4 % 128;
    ((float4*)out)[row * 256 + c4] = ((const float4*)x)[idx4];
}

// ---------------------------------------------------------------------------
extern "C" void kernel_launch(void* const* d_in, const int* in_sizes, int n_in,
                              void* d_out, int out_size)
{
    const float* x  = (const float*)d_in[0];
    const float* Wq = (const float*)d_in[1];
    const float* bq = (const float*)d_in[2];
    const float* Wk = (const float*)d_in[3];
    const float* bk = (const float*)d_in[4];
    const float* Wv = (const float*)d_in[5];
    const float* bv = (const float*)d_in[6];
    float* out = (float*)d_out;

    qkv_kernel<<<dim3(4, 128, 3), 256>>>(x, Wq, bq, Wk, bk, Wv, bv);
    scores_kernel<<<dim3(16, 16, 8), 256>>>();
    colstats_kernel<<<dim3(64, 8), 256>>>();
    attnv_kernel<<<dim3(4, 16, 8), 256>>>(out);
    copyx_kernel<<<dim3(8192), 256>>>(x, out);
}

// round 2
// speedup vs baseline: 2.6936x; 2.6936x over previous
#include <cuda_runtime.h>
#include <math.h>

#define NB 8
#define NT 2048
#define NC 512
#define NK 512
#define SCALE 0.044194173824159216f  // 1/sqrt(512)

// Scratch (device globals: allocation-free per harness rules)
static __device__ float g_q[(size_t)NB * NT * NK];
static __device__ float g_k[(size_t)NB * NT * NK];
static __device__ float g_v[(size_t)NB * NT * NK];
static __device__ float g_S[(size_t)NB * NT * NT];
static __device__ float g_m[NB * NT];
static __device__ float g_iz[NB * NT];

__device__ __forceinline__ unsigned f2tf(float f) {
    unsigned u;
    asm("cvt.rna.tf32.f32 %0, %1;" : "=r"(u) : "f"(f));
    return u;
}

#define MMA_TF32(c, a, b)                                                   \
    asm volatile(                                                           \
        "mma.sync.aligned.m16n8k8.row.col.f32.tf32.tf32.f32 "               \
        "{%0,%1,%2,%3},{%4,%5,%6,%7},{%8,%9},{%0,%1,%2,%3};\n"              \
        : "+f"((c)[0]), "+f"((c)[1]), "+f"((c)[2]), "+f"((c)[3])            \
        : "r"((a)[0]), "r"((a)[1]), "r"((a)[2]), "r"((a)[3]),               \
          "r"((b)[0]), "r"((b)[1]))

// ---------------------------------------------------------------------------
// Kernel 1: q/k/v = x @ W^T + b   (NT GEMM, M=16384, N=512, K=512)
// tf32 mma.sync: 128x128 CTA tile, BK=32, 8 warps (2x4), warp tile 64x32.
// ---------------------------------------------------------------------------
__global__ void __launch_bounds__(256, 2) qkv_kernel(
    const float* __restrict__ x,
    const float* __restrict__ Wq, const float* __restrict__ bq,
    const float* __restrict__ Wk, const float* __restrict__ bk,
    const float* __restrict__ Wv, const float* __restrict__ bv)
{
    const int which = blockIdx.z;
    const float* W    = (which == 0) ? Wq : (which == 1) ? Wk : Wv;
    const float* bias = (which == 0) ? bq : (which == 1) ? bk : bv;
    float* out        = (which == 0) ? g_q : (which == 1) ? g_k : g_v;

    const int m0 = blockIdx.y * 128;
    const int n0 = blockIdx.x * 128;

    __shared__ __align__(16) unsigned As[128][36];  // [m][k], pad 36 -> conflict-free frag loads
    __shared__ __align__(16) unsigned Bs[128][36];  // [n][k]

    const int tid  = threadIdx.x;
    const int wid  = tid >> 5;
    const int lane = tid & 31;
    const int gid  = lane >> 2;   // 0..7
    const int tig  = lane & 3;    // 0..3
    const int wm   = (wid & 1) * 64;
    const int wn   = (wid >> 1) * 32;

    float acc[4][4][4] = {};

    for (int k0 = 0; k0 < NC; k0 += 32) {
        #pragma unroll
        for (int i = 0; i < 4; i++) {
            int idx = i * 256 + tid;      // 0..1023
            int row = idx >> 3;
            int c4  = (idx & 7) * 4;
            float4 a = *(const float4*)(x + (size_t)(m0 + row) * NC + k0 + c4);
            uint4 ua = { f2tf(a.x), f2tf(a.y), f2tf(a.z), f2tf(a.w) };
            *(uint4*)&As[row][c4] = ua;
            float4 b = *(const float4*)(W + (size_t)(n0 + row) * NC + k0 + c4);
            uint4 ub = { f2tf(b.x), f2tf(b.y), f2tf(b.z), f2tf(b.w) };
            *(uint4*)&Bs[row][c4] = ub;
        }
        __syncthreads();

        #pragma unroll
        for (int ks = 0; ks < 4; ks++) {
            const int kc = ks * 8;
            unsigned af[4][4];
            #pragma unroll
            for (int mt = 0; mt < 4; mt++) {
                int r = wm + mt * 16 + gid;
                af[mt][0] = As[r    ][kc + tig];
                af[mt][1] = As[r + 8][kc + tig];
                af[mt][2] = As[r    ][kc + tig + 4];
                af[mt][3] = As[r + 8][kc + tig + 4];
            }
            unsigned bf[4][2];
            #pragma unroll
            for (int nt = 0; nt < 4; nt++) {
                int n = wn + nt * 8 + gid;
                bf[nt][0] = Bs[n][kc + tig];
                bf[nt][1] = Bs[n][kc + tig + 4];
            }
            #pragma unroll
            for (int mt = 0; mt < 4; mt++)
                #pragma unroll
                for (int nt = 0; nt < 4; nt++)
                    MMA_TF32(acc[mt][nt], af[mt], bf[nt]);
        }
        __syncthreads();
    }

    #pragma unroll
    for (int mt = 0; mt < 4; mt++) {
        #pragma unroll
        for (int nt = 0; nt < 4; nt++) {
            int m = m0 + wm + mt * 16 + gid;
            int n = n0 + wn + nt * 8 + 2 * tig;
            float b0 = bias[n], b1 = bias[n + 1];
            float2 v0 = { acc[mt][nt][0] + b0, acc[mt][nt][1] + b1 };
            float2 v1 = { acc[mt][nt][2] + b0, acc[mt][nt][3] + b1 };
            *(float2*)(out + (size_t)m * NK + n) = v0;
            *(float2*)(out + (size_t)(m + 8) * NK + n) = v1;
        }
    }
}

// ---------------------------------------------------------------------------
// Kernel 2: S = (q @ k^T) * SCALE, lower-triangle tiles only (per batch).
// Grid.x enumerates the 136 lower tiles directly.
// ---------------------------------------------------------------------------
__global__ void __launch_bounds__(256, 2) scores_kernel()
{
    const int b = blockIdx.y;
    // decode linear lower-tri tile index -> (qt, st)
    int xi = blockIdx.x;
    int qt = (int)((sqrtf(8.0f * xi + 1.0f) - 1.0f) * 0.5f);
    while ((qt + 1) * (qt + 2) / 2 <= xi) qt++;
    while (qt * (qt + 1) / 2 > xi) qt--;
    const int st = xi - qt * (qt + 1) / 2;

    const float* A  = g_q + (size_t)b * NT * NK;
    const float* Bm = g_k + (size_t)b * NT * NK;
    float* S = g_S + (size_t)b * NT * NT;

    const int m0 = qt * 128;
    const int n0 = st * 128;

    __shared__ __align__(16) unsigned As[128][36];
    __shared__ __align__(16) unsigned Bs[128][36];

    const int tid  = threadIdx.x;
    const int wid  = tid >> 5;
    const int lane = tid & 31;
    const int gid  = lane >> 2;
    const int tig  = lane & 3;
    const int wm   = (wid & 1) * 64;
    const int wn   = (wid >> 1) * 32;

    float acc[4][4][4] = {};

    for (int k0 = 0; k0 < NK; k0 += 32) {
        #pragma unroll
        for (int i = 0; i < 4; i++) {
            int idx = i * 256 + tid;
            int row = idx >> 3;
            int c4  = (idx & 7) * 4;
            float4 a = *(const float4*)(A + (size_t)(m0 + row) * NK + k0 + c4);
            uint4 ua = { f2tf(a.x), f2tf(a.y), f2tf(a.z), f2tf(a.w) };
            *(uint4*)&As[row][c4] = ua;
            float4 bb = *(const float4*)(Bm + (size_t)(n0 + row) * NK + k0 + c4);
            uint4 ub = { f2tf(bb.x), f2tf(bb.y), f2tf(bb.z), f2tf(bb.w) };
            *(uint4*)&Bs[row][c4] = ub;
        }
        __syncthreads();

        #pragma unroll
        for (int ks = 0; ks < 4; ks++) {
            const int kc = ks * 8;
            unsigned af[4][4];
            #pragma unroll
            for (int mt = 0; mt < 4; mt++) {
                int r = wm + mt * 16 + gid;
                af[mt][0] = As[r    ][kc + tig];
                af[mt][1] = As[r + 8][kc + tig];
                af[mt][2] = As[r    ][kc + tig + 4];
                af[mt][3] = As[r + 8][kc + tig + 4];
            }
            unsigned bf[4][2];
            #pragma unroll
            for (int nt = 0; nt < 4; nt++) {
                int n = wn + nt * 8 + gid;
                bf[nt][0] = Bs[n][kc + tig];
                bf[nt][1] = Bs[n][kc + tig + 4];
            }
            #pragma unroll
            for (int mt = 0; mt < 4; mt++)
                #pragma unroll
                for (int nt = 0; nt < 4; nt++)
                    MMA_TF32(acc[mt][nt], af[mt], bf[nt]);
        }
        __syncthreads();
    }

    #pragma unroll
    for (int mt = 0; mt < 4; mt++) {
        #pragma unroll
        for (int nt = 0; nt < 4; nt++) {
            int m = m0 + wm + mt * 16 + gid;
            int n = n0 + wn + nt * 8 + 2 * tig;
            float2 v0 = { acc[mt][nt][0] * SCALE, acc[mt][nt][1] * SCALE };
            float2 v1 = { acc[mt][nt][2] * SCALE, acc[mt][nt][3] * SCALE };
            *(float2*)(S + (size_t)m * NT + n) = v0;
            *(float2*)(S + (size_t)(m + 8) * NT + n) = v1;
        }
    }
}

// ---------------------------------------------------------------------------
// Kernel 3: per-column (key-axis) softmax stats over the QUERY axis.
// ---------------------------------------------------------------------------
__global__ void __launch_bounds__(256) colstats_kernel()
{
    const int b = blockIdx.y;
    const int c = threadIdx.x & 31;
    const int rl = threadIdx.x >> 5;     // 0..7
    const int col = blockIdx.x * 32 + c;
    const float* S = g_S + (size_t)b * NT * NT;

    __shared__ float red[8][32];

    const int qstart = (col & ~7) + rl;

    float m = -INFINITY;
    for (int q = qstart; q < NT; q += 8)
        if (q >= col) m = fmaxf(m, S[(size_t)q * NT + col]);

    red[rl][c] = m;
    __syncthreads();
    if (rl == 0) {
        #pragma unroll
        for (int r = 1; r < 8; r++) m = fmaxf(m, red[r][c]);
        red[0][c] = m;
    }
    __syncthreads();
    const float cm = red[0][c];
    __syncthreads();

    float z = 0.f;
    for (int q = qstart; q < NT; q += 8)
        if (q >= col) z += __expf(S[(size_t)q * NT + col] - cm);

    red[rl][c] = z;
    __syncthreads();
    if (rl == 0) {
        #pragma unroll
        for (int r = 1; r < 8; r++) z += red[r][c];
        g_m[b * NT + col] = cm;
        g_iz[b * NT + col] = 1.f / z;
    }
}

// ---------------------------------------------------------------------------
// Kernel 4: attn = P @ V, P[q,s] = (s<=q) ? exp(S[q,s]-m_s)*invZ_s : 0
// tf32 mma; A tile (P) built on the fly; triangular k-range.
// qt processed in DESCENDING order (big blocks first) for wave balance.
// ---------------------------------------------------------------------------
__global__ void __launch_bounds__(256, 2) attnv_kernel(float* __restrict__ out)
{
    const int b  = blockIdx.z;
    const int qt = gridDim.y - 1 - blockIdx.y;   // big tiles scheduled first
    const int n0 = blockIdx.x * 128;

    const float* S   = g_S + (size_t)b * NT * NT;
    const float* V   = g_v + (size_t)b * NT * NK;
    const float* cm  = g_m + b * NT;
    const float* ciz = g_iz + b * NT;

    const int m0   = qt * 128;
    const int kend = m0 + 128;

    __shared__ __align__(16) unsigned As[128][36];   // P[q][s-chunk]
    __shared__ __align__(16) unsigned Bs[32][136];   // V[s-chunk][n], pad 136

    const int tid  = threadIdx.x;
    const int wid  = tid >> 5;
    const int lane = tid & 31;
    const int gid  = lane >> 2;
    const int tig  = lane & 3;
    const int wm   = (wid & 1) * 64;
    const int wn   = (wid >> 1) * 32;

    float acc[4][4][4] = {};

    for (int k0 = 0; k0 < kend; k0 += 32) {
        // Stage A = P tile: 128 q-rows x 32 s-cols
        #pragma unroll
        for (int i = 0; i < 4; i++) {
            int idx = i * 256 + tid;
            int row = idx >> 3;
            int c4  = (idx & 7) * 4;
            int q = m0 + row;
            int s = k0 + c4;
            float4 sv = *(const float4*)(S + (size_t)q * NT + s);
            uint4 ua;
            ua.x = f2tf((s + 0 <= q) ? __expf(sv.x - cm[s + 0]) * ciz[s + 0] : 0.f);
            ua.y = f2tf((s + 1 <= q) ? __expf(sv.y - cm[s + 1]) * ciz[s + 1] : 0.f);
            ua.z = f2tf((s + 2 <= q) ? __expf(sv.z - cm[s + 2]) * ciz[s + 2] : 0.f);
            ua.w = f2tf((s + 3 <= q) ? __expf(sv.w - cm[s + 3]) * ciz[s + 3] : 0.f);
            *(uint4*)&As[row][c4] = ua;
        }
        // Stage B = V chunk: 32 s-rows x 128 n-cols
        #pragma unroll
        for (int i = 0; i < 4; i++) {
            int idx = i * 256 + tid;
            int row = idx >> 5;
            int c4  = (idx & 31) * 4;
            float4 vv = *(const float4*)(V + (size_t)(k0 + row) * NK + n0 + c4);
            uint4 ub = { f2tf(vv.x), f2tf(vv.y), f2tf(vv.z), f2tf(vv.w) };
            *(uint4*)&Bs[row][c4] = ub;
        }
        __syncthreads();

        #pragma unroll
        for (int ks = 0; ks < 4; ks++) {
            const int kc = ks * 8;
            unsigned af[4][4];
            #pragma unroll
            for (int mt = 0; mt < 4; mt++) {
                int r = wm + mt * 16 + gid;
                af[mt][0] = As[r    ][kc + tig];
                af[mt][1] = As[r + 8][kc + tig];
                af[mt][2] = As[r    ][kc + tig + 4];
                af[mt][3] = As[r + 8][kc + tig + 4];
            }
            unsigned bf[4][2];
            #pragma unroll
            for (int nt = 0; nt < 4; nt++) {
                int n = wn + nt * 8 + gid;
                bf[nt][0] = Bs[kc + tig    ][n];
                bf[nt][1] = Bs[kc + tig + 4][n];
            }
            #pragma unroll
            for (int mt = 0; mt < 4; mt++)
                #pragma unroll
                for (int nt = 0; nt < 4; nt++)
                    MMA_TF32(acc[mt][nt], af[mt], bf[nt]);
        }
        __syncthreads();
    }

    #pragma unroll
    for (int mt = 0; mt < 4; mt++) {
        #pragma unroll
        for (int nt = 0; nt < 4; nt++) {
            int q = m0 + wm + mt * 16 + gid;
            int n = n0 + wn + nt * 8 + 2 * tig;
            float2 v0 = { acc[mt][nt][0], acc[mt][nt][1] };
            float2 v1 = { acc[mt][nt][2], acc[mt][nt][3] };
            *(float2*)(out + ((size_t)b * NT + q) * 1024 + 512 + n) = v0;
            *(float2*)(out + ((size_t)b * NT + q + 8) * 1024 + 512 + n) = v1;
        }
    }
}

// ---------------------------------------------------------------------------
// Kernel 5: out[..., 0:512] = x
// ---------------------------------------------------------------------------
__global__ void __launch_bounds__(256) copyx_kernel(
    const float* __restrict__ x, float* __restrict__ out)
{
    size_t idx4 = (size_t)blockIdx.x * blockDim.x + threadIdx.x;
    size_t row = idx4 / 128;
    size_t c4  = idx4 % 128;
    ((float4*)out)[row * 256 + c4] = ((const float4*)x)[idx4];
}

// ---------------------------------------------------------------------------
extern "C" void kernel_launch(void* const* d_in, const int* in_sizes, int n_in,
                              void* d_out, int out_size)
{
    const float* x  = (const float*)d_in[0];
    const float* Wq = (const float*)d_in[1];
    const float* bq = (const float*)d_in[2];
    const float* Wk = (const float*)d_in[3];
    const float* bk = (const float*)d_in[4];
    const float* Wv = (const float*)d_in[5];
    const float* bv = (const float*)d_in[6];
    float* out = (float*)d_out;

    qkv_kernel<<<dim3(4, 128, 3), 256>>>(x, Wq, bq, Wk, bk, Wv, bv);
    scores_kernel<<<dim3(136, 8), 256>>>();
    colstats_kernel<<<dim3(64, 8), 256>>>();
    attnv_kernel<<<dim3(4, 16, 8), 256>>>(out);
    copyx_kernel<<<dim3(8192), 256>>>(x, out);
}

// round 3
// speedup vs baseline: 3.4948x; 1.2975x over previous
#include <cuda_runtime.h>
#include <math.h>

#define NB 8
#define NT 2048
#define NC 512
#define NK 512
#define SCALE 0.044194173824159216f  // 1/sqrt(512)

// Scratch (device globals: allocation-free per harness rules)
static __device__ float g_q[(size_t)NB * NT * NK];
static __device__ float g_k[(size_t)NB * NT * NK];
static __device__ float g_v[(size_t)NB * NT * NK];
static __device__ float g_S[(size_t)NB * NT * NT];   // scores, then P in-place

__device__ __forceinline__ unsigned f2tf(float f) {
    unsigned u;
    asm("cvt.rna.tf32.f32 %0, %1;" : "=r"(u) : "f"(f));
    return u;
}

__device__ __forceinline__ void cpa16(float* dst_smem, const float* src) {
    unsigned s = (unsigned)__cvta_generic_to_shared(dst_smem);
    asm volatile("cp.async.ca.shared.global [%0], [%1], 16;\n" :: "r"(s), "l"(src));
}
#define CP_COMMIT() asm volatile("cp.async.commit_group;\n" ::: "memory")
#define CP_WAIT0()  asm volatile("cp.async.wait_group 0;\n" ::: "memory")

#define MMA_TF32(c, a, b)                                                   \
    asm volatile(                                                           \
        "mma.sync.aligned.m16n8k8.row.col.f32.tf32.tf32.f32 "               \
        "{%0,%1,%2,%3},{%4,%5,%6,%7},{%8,%9},{%0,%1,%2,%3};\n"              \
        : "+f"((c)[0]), "+f"((c)[1]), "+f"((c)[2]), "+f"((c)[3])            \
        : "r"((a)[0]), "r"((a)[1]), "r"((a)[2]), "r"((a)[3]),               \
          "r"((b)[0]), "r"((b)[1]))

// Shared compute step for the [128][36]-layout A/B tiles (NT GEMMs).
#define COMPUTE_NT(AS, BS)                                                  \
    _Pragma("unroll")                                                       \
    for (int ks = 0; ks < 4; ks++) {                                        \
        const int kc = ks * 8;                                              \
        unsigned af[4][4];                                                  \
        _Pragma("unroll")                                                   \
        for (int mt = 0; mt < 4; mt++) {                                    \
            int r = wm + mt * 16 + gid;                                     \
            af[mt][0] = __float_as_uint((AS)[r    ][kc + tig]);             \
            af[mt][1] = __float_as_uint((AS)[r + 8][kc + tig]);             \
            af[mt][2] = __float_as_uint((AS)[r    ][kc + tig + 4]);         \
            af[mt][3] = __float_as_uint((AS)[r + 8][kc + tig + 4]);         \
        }                                                                   \
        unsigned bf[4][2];                                                  \
        _Pragma("unroll")                                                   \
        for (int nt = 0; nt < 4; nt++) {                                    \
            int n = wn + nt * 8 + gid;                                      \
            bf[nt][0] = __float_as_uint((BS)[n][kc + tig]);                 \
            bf[nt][1] = __float_as_uint((BS)[n][kc + tig + 4]);             \
        }                                                                   \
        _Pragma("unroll")                                                   \
        for (int mt = 0; mt < 4; mt++)                                      \
            _Pragma("unroll")                                               \
            for (int nt = 0; nt < 4; nt++)                                  \
                MMA_TF32(acc[mt][nt], af[mt], bf[nt]);                      \
    }

// ---------------------------------------------------------------------------
// Kernel 1: q/k/v = x @ W^T + b   (NT GEMM, M=16384, N=512, K=512)
// cp.async double-buffered, 128x128 CTA tile, BK=32, 8 warps, warp 64x32.
// ---------------------------------------------------------------------------
__global__ void __launch_bounds__(256, 2) qkv_kernel(
    const float* __restrict__ x,
    const float* __restrict__ Wq, const float* __restrict__ bq,
    const float* __restrict__ Wk, const float* __restrict__ bk,
    const float* __restrict__ Wv, const float* __restrict__ bv)
{
    const int which = blockIdx.z;
    const float* W    = (which == 0) ? Wq : (which == 1) ? Wk : Wv;
    const float* bias = (which == 0) ? bq : (which == 1) ? bk : bv;
    float* out        = (which == 0) ? g_q : (which == 1) ? g_k : g_v;

    const int m0 = blockIdx.y * 128;
    const int n0 = blockIdx.x * 128;

    extern __shared__ float sm[];
    float (*As)[128][36] = (float (*)[128][36])sm;
    float (*Bs)[128][36] = (float (*)[128][36])(sm + 2 * 128 * 36);

    const int tid  = threadIdx.x;
    const int wid  = tid >> 5;
    const int lane = tid & 31;
    const int gid  = lane >> 2;
    const int tig  = lane & 3;
    const int wm   = (wid & 1) * 64;
    const int wn   = (wid >> 1) * 32;

    const int row = tid >> 3;          // staging row for this thread (x4 chunks)
    const int c4  = (tid & 7) * 4;

    float acc[4][4][4] = {};

    // prologue: stage k0 = 0 into buffer 0
    #pragma unroll
    for (int i = 0; i < 4; i++) {
        int r = row + i * 32;
        cpa16(&As[0][r][c4], x + (size_t)(m0 + r) * NC + c4);
        cpa16(&Bs[0][r][c4], W + (size_t)(n0 + r) * NC + c4);
    }
    CP_COMMIT();

    int p = 0;
    for (int it = 0; it < 16; it++) {
        CP_WAIT0();
        __syncthreads();
        if (it + 1 < 16) {
            int k0 = (it + 1) * 32;
            #pragma unroll
            for (int i = 0; i < 4; i++) {
                int r = row + i * 32;
                cpa16(&As[p ^ 1][r][c4], x + (size_t)(m0 + r) * NC + k0 + c4);
                cpa16(&Bs[p ^ 1][r][c4], W + (size_t)(n0 + r) * NC + k0 + c4);
            }
            CP_COMMIT();
        }
        COMPUTE_NT(As[p], Bs[p]);
        p ^= 1;
    }

    #pragma unroll
    for (int mt = 0; mt < 4; mt++) {
        #pragma unroll
        for (int nt = 0; nt < 4; nt++) {
            int m = m0 + wm + mt * 16 + gid;
            int n = n0 + wn + nt * 8 + 2 * tig;
            float b0 = bias[n], b1 = bias[n + 1];
            float2 v0 = { acc[mt][nt][0] + b0, acc[mt][nt][1] + b1 };
            float2 v1 = { acc[mt][nt][2] + b0, acc[mt][nt][3] + b1 };
            *(float2*)(out + (size_t)m * NK + n) = v0;
            *(float2*)(out + (size_t)(m + 8) * NK + n) = v1;
        }
    }
}

// ---------------------------------------------------------------------------
// Kernel 2: S = (q @ k^T) * SCALE, lower-triangle tiles only (per batch).
// ---------------------------------------------------------------------------
__global__ void __launch_bounds__(256, 2) scores_kernel()
{
    const int b = blockIdx.y;
    int xi = blockIdx.x;
    int qt = (int)((sqrtf(8.0f * xi + 1.0f) - 1.0f) * 0.5f);
    while ((qt + 1) * (qt + 2) / 2 <= xi) qt++;
    while (qt * (qt + 1) / 2 > xi) qt--;
    const int st = xi - qt * (qt + 1) / 2;

    const float* A  = g_q + (size_t)b * NT * NK;
    const float* Bm = g_k + (size_t)b * NT * NK;
    float* S = g_S + (size_t)b * NT * NT;

    const int m0 = qt * 128;
    const int n0 = st * 128;

    extern __shared__ float sm[];
    float (*As)[128][36] = (float (*)[128][36])sm;
    float (*Bs)[128][36] = (float (*)[128][36])(sm + 2 * 128 * 36);

    const int tid  = threadIdx.x;
    const int wid  = tid >> 5;
    const int lane = tid & 31;
    const int gid  = lane >> 2;
    const int tig  = lane & 3;
    const int wm   = (wid & 1) * 64;
    const int wn   = (wid >> 1) * 32;

    const int row = tid >> 3;
    const int c4  = (tid & 7) * 4;

    float acc[4][4][4] = {};

    #pragma unroll
    for (int i = 0; i < 4; i++) {
        int r = row + i * 32;
        cpa16(&As[0][r][c4], A  + (size_t)(m0 + r) * NK + c4);
        cpa16(&Bs[0][r][c4], Bm + (size_t)(n0 + r) * NK + c4);
    }
    CP_COMMIT();

    int p = 0;
    for (int it = 0; it < 16; it++) {
        CP_WAIT0();
        __syncthreads();
        if (it + 1 < 16) {
            int k0 = (it + 1) * 32;
            #pragma unroll
            for (int i = 0; i < 4; i++) {
                int r = row + i * 32;
                cpa16(&As[p ^ 1][r][c4], A  + (size_t)(m0 + r) * NK + k0 + c4);
                cpa16(&Bs[p ^ 1][r][c4], Bm + (size_t)(n0 + r) * NK + k0 + c4);
            }
            CP_COMMIT();
        }
        COMPUTE_NT(As[p], Bs[p]);
        p ^= 1;
    }

    #pragma unroll
    for (int mt = 0; mt < 4; mt++) {
        #pragma unroll
        for (int nt = 0; nt < 4; nt++) {
            int m = m0 + wm + mt * 16 + gid;
            int n = n0 + wn + nt * 8 + 2 * tig;
            float2 v0 = { acc[mt][nt][0] * SCALE, acc[mt][nt][1] * SCALE };
            float2 v1 = { acc[mt][nt][2] * SCALE, acc[mt][nt][3] * SCALE };
            *(float2*)(S + (size_t)m * NT + n) = v0;
            *(float2*)(S + (size_t)(m + 8) * NT + n) = v1;
        }
    }
}

// ---------------------------------------------------------------------------
// Kernel 3: column softmax stats over QUERY axis + write P in place.
// Pass 1: m_s = max_{q>=s} S[q,s]; Pass 2: Z_s; Pass 3: S[q,s] <- P[q,s]
// (zeroing the strict-upper part of the diagonal 128-block so attnv can
//  read full tiles unmasked).
// ---------------------------------------------------------------------------
__global__ void __launch_bounds__(256) colstats_kernel()
{
    const int b = blockIdx.y;
    const int c = threadIdx.x & 31;
    const int rl = threadIdx.x >> 5;     // 0..7
    const int col = blockIdx.x * 32 + c;
    float* S = g_S + (size_t)b * NT * NT;

    __shared__ float red[8][32];

    const int qstart = (col & ~7) + rl;

    float m = -INFINITY;
    for (int q = qstart; q < NT; q += 8)
        if (q >= col) m = fmaxf(m, S[(size_t)q * NT + col]);

    red[rl][c] = m;
    __syncthreads();
    if (rl == 0) {
        #pragma unroll
        for (int r = 1; r < 8; r++) m = fmaxf(m, red[r][c]);
        red[0][c] = m;
    }
    __syncthreads();
    const float cm = red[0][c];
    __syncthreads();

    float z = 0.f;
    for (int q = qstart; q < NT; q += 8)
        if (q >= col) z += __expf(S[(size_t)q * NT + col] - cm);

    red[rl][c] = z;
    __syncthreads();
    if (rl == 0) {
        #pragma unroll
        for (int r = 1; r < 8; r++) z += red[r][c];
        red[0][c] = 1.f / z;
    }
    __syncthreads();
    const float ciz = red[0][c];

    // Pass 3: write P (tf32-rounded) over the region attnv will read:
    // q from the start of col's 128-block (zeros above diagonal) to NT.
    const int qb = (col & ~127) + rl;
    for (int q = qb; q < NT; q += 8) {
        float p = 0.f;
        if (q >= col)
            p = __expf(S[(size_t)q * NT + col] - cm) * ciz;
        S[(size_t)q * NT + col] = __uint_as_float(f2tf(p));
    }
}

// ---------------------------------------------------------------------------
// Kernel 4: attn = P @ V  — pure tf32 GEMM over triangular k-range.
// ---------------------------------------------------------------------------
__global__ void __launch_bounds__(256, 2) attnv_kernel(float* __restrict__ out)
{
    const int b  = blockIdx.z;
    const int qt = gridDim.y - 1 - blockIdx.y;   // big tiles first
    const int n0 = blockIdx.x * 128;

    const float* P = g_S + (size_t)b * NT * NT;
    const float* V = g_v + (size_t)b * NT * NK;

    const int m0 = qt * 128;
    const int KT = 4 * (qt + 1);                 // k-iters of 32

    extern __shared__ float sm[];
    float (*As)[128][36]  = (float (*)[128][36])sm;        // P[q][s]
    float (*Bs)[32][136]  = (float (*)[32][136])(sm + 2 * 128 * 36);  // V[s][n]

    const int tid  = threadIdx.x;
    const int wid  = tid >> 5;
    const int lane = tid & 31;
    const int gid  = lane >> 2;
    const int tig  = lane & 3;
    const int wm   = (wid & 1) * 64;
    const int wn   = (wid >> 1) * 32;

    const int arow = tid >> 3;
    const int ac4  = (tid & 7) * 4;
    const int brow = tid >> 5;
    const int bc4  = (tid & 31) * 4;

    float acc[4][4][4] = {};

    #pragma unroll
    for (int i = 0; i < 4; i++) {
        int r = arow + i * 32;
        cpa16(&As[0][r][ac4], P + (size_t)(m0 + r) * NT + ac4);
        int br = brow + i * 8;
        cpa16(&Bs[0][br][bc4], V + (size_t)br * NK + n0 + bc4);
    }
    CP_COMMIT();

    int p = 0;
    for (int it = 0; it < KT; it++) {
        CP_WAIT0();
        __syncthreads();
        if (it + 1 < KT) {
            int k0 = (it + 1) * 32;
            #pragma unroll
            for (int i = 0; i < 4; i++) {
                int r = arow + i * 32;
                cpa16(&As[p ^ 1][r][ac4], P + (size_t)(m0 + r) * NT + k0 + ac4);
                int br = brow + i * 8;
                cpa16(&Bs[p ^ 1][br][bc4], V + (size_t)(k0 + br) * NK + n0 + bc4);
            }
            CP_COMMIT();
        }
        // compute: A[128][36] row-major (q x s), B[32][136] (s x n)
        #pragma unroll
        for (int ks = 0; ks < 4; ks++) {
            const int kc = ks * 8;
            unsigned af[4][4];
            #pragma unroll
            for (int mt = 0; mt < 4; mt++) {
                int r = wm + mt * 16 + gid;
                af[mt][0] = __float_as_uint(As[p][r    ][kc + tig]);
                af[mt][1] = __float_as_uint(As[p][r + 8][kc + tig]);
                af[mt][2] = __float_as_uint(As[p][r    ][kc + tig + 4]);
                af[mt][3] = __float_as_uint(As[p][r + 8][kc + tig + 4]);
            }
            unsigned bf[4][2];
            #pragma unroll
            for (int nt = 0; nt < 4; nt++) {
                int n = wn + nt * 8 + gid;
                bf[nt][0] = __float_as_uint(Bs[p][kc + tig    ][n]);
                bf[nt][1] = __float_as_uint(Bs[p][kc + tig + 4][n]);
            }
            #pragma unroll
            for (int mt = 0; mt < 4; mt++)
                #pragma unroll
                for (int nt = 0; nt < 4; nt++)
                    MMA_TF32(acc[mt][nt], af[mt], bf[nt]);
        }
        p ^= 1;
    }

    #pragma unroll
    for (int mt = 0; mt < 4; mt++) {
        #pragma unroll
        for (int nt = 0; nt < 4; nt++) {
            int q = m0 + wm + mt * 16 + gid;
            int n = n0 + wn + nt * 8 + 2 * tig;
            float2 v0 = { acc[mt][nt][0], acc[mt][nt][1] };
            float2 v1 = { acc[mt][nt][2], acc[mt][nt][3] };
            *(float2*)(out + ((size_t)b * NT + q) * 1024 + 512 + n) = v0;
            *(float2*)(out + ((size_t)b * NT + q + 8) * 1024 + 512 + n) = v1;
        }
    }
}

// ---------------------------------------------------------------------------
// Kernel 5: out[..., 0:512] = x
// ---------------------------------------------------------------------------
__global__ void __launch_bounds__(256) copyx_kernel(
    const float* __restrict__ x, float* __restrict__ out)
{
    size_t idx4 = (size_t)blockIdx.x * blockDim.x + threadIdx.x;
    size_t row = idx4 / 128;
    size_t c4  = idx4 % 128;
    ((float4*)out)[row * 256 + c4] = ((const float4*)x)[idx4];
}

// ---------------------------------------------------------------------------
extern "C" void kernel_launch(void* const* d_in, const int* in_sizes, int n_in,
                              void* d_out, int out_size)
{
    const float* x  = (const float*)d_in[0];
    const float* Wq = (const float*)d_in[1];
    const float* bq = (const float*)d_in[2];
    const float* Wk = (const float*)d_in[3];
    const float* bk = (const float*)d_in[4];
    const float* Wv = (const float*)d_in[5];
    const float* bv = (const float*)d_in[6];
    float* out = (float*)d_out;

    const int smem_nt   = 2 * 128 * 36 * 4 * 2;               // 73728 B
    const int smem_attn = (2 * 128 * 36 + 2 * 32 * 136) * 4;  // 71680 B
    cudaFuncSetAttribute(qkv_kernel,    cudaFuncAttributeMaxDynamicSharedMemorySize, smem_nt);
    cudaFuncSetAttribute(scores_kernel, cudaFuncAttributeMaxDynamicSharedMemorySize, smem_nt);
    cudaFuncSetAttribute(attnv_kernel,  cudaFuncAttributeMaxDynamicSharedMemorySize, smem_attn);

    qkv_kernel<<<dim3(4, 128, 3), 256, smem_nt>>>(x, Wq, bq, Wk, bk, Wv, bv);
    scores_kernel<<<dim3(136, 8), 256, smem_nt>>>();
    colstats_kernel<<<dim3(64, 8), 256>>>();
    attnv_kernel<<<dim3(4, 16, 8), 256, smem_attn>>>(out);
    copyx_kernel<<<dim3(8192), 256>>>(x, out);
}

// round 5
// speedup vs baseline: 3.5435x; 1.0139x over previous
#include <cuda_runtime.h>
#include <cuda_bf16.h>
#include <math.h>
#include <stdint.h>

#define NB 8
#define NT 2048
#define NC 512
#define NK 512
#define SCALE 0.044194173824159216f  // 1/sqrt(512)

// Scratch (device globals: allocation-free per harness rules)
static __device__ __nv_bfloat16 g_xb[(size_t)NB * NT * NC];
static __device__ __nv_bfloat16 g_wb[3 * 512 * 512];
static __device__ __nv_bfloat16 g_qb[(size_t)NB * NT * NK];
static __device__ __nv_bfloat16 g_kb[(size_t)NB * NT * NK];
static __device__ __nv_bfloat16 g_vb[(size_t)NB * NT * NK];
static __device__ __nv_bfloat16 g_vT[(size_t)NB * NK * NT];  // [b*512+n][s]
static __device__ float         g_S [(size_t)NB * NT * NT];  // fp32 scores
static __device__ __nv_bfloat16 g_P [(size_t)NB * NT * NT];  // bf16 probs

// ---------------------------------------------------------------------------
// helpers
// ---------------------------------------------------------------------------
__device__ __forceinline__ void cpa16(void* dst_smem, const void* src) {
    unsigned s = (unsigned)__cvta_generic_to_shared(dst_smem);
    asm volatile("cp.async.ca.shared.global [%0], [%1], 16;\n" :: "r"(s), "l"(src));
}
#define CP_COMMIT() asm volatile("cp.async.commit_group;\n" ::: "memory")
#define CP_WAIT0()  asm volatile("cp.async.wait_group 0;\n" ::: "memory")
#define CP_WAIT1()  asm volatile("cp.async.wait_group 1;\n" ::: "memory")

#define MMA_BF16(c, a, b)                                                   \
    asm volatile(                                                           \
        "mma.sync.aligned.m16n8k16.row.col.f32.bf16.bf16.f32 "              \
        "{%0,%1,%2,%3},{%4,%5,%6,%7},{%8,%9},{%0,%1,%2,%3};\n"              \
        : "+f"((c)[0]), "+f"((c)[1]), "+f"((c)[2]), "+f"((c)[3])            \
        : "r"((a)[0]), "r"((a)[1]), "r"((a)[2]), "r"((a)[3]),               \
          "r"((b)[0]), "r"((b)[1]))

// Stage layout: A tile 128 rows x 32 bf16, row stride 40 bf16 (80B) -> 10240B
// B tile same -> stage = 20480B; 3 stages = 61440B dynamic smem.
#define ROWB     80
#define A_BYTES  10240
#define STAGE_B  20480

// stage one 128x32 bf16 tile pair (A,B) via cp.async; 4 chunks of 16B/row total
__device__ __forceinline__ void stage_issue(
    char* smA, const __nv_bfloat16* Ag, size_t asr,
    char* smB, const __nv_bfloat16* Bg, size_t bsr, int k0, int tid)
{
    const int r  = tid >> 1;
    const int cb = (tid & 1) * 16;  // bf16 col base (0 or 16)
    cpa16(smA + r * ROWB + cb * 2,      Ag + (size_t)r * asr + k0 + cb);
    cpa16(smA + r * ROWB + cb * 2 + 16, Ag + (size_t)r * asr + k0 + cb + 8);
    cpa16(smB + r * ROWB + cb * 2,      Bg + (size_t)r * bsr + k0 + cb);
    cpa16(smB + r * ROWB + cb * 2 + 16, Bg + (size_t)r * bsr + k0 + cb + 8);
    CP_COMMIT();
}

// compute one staged 128x128x32 buffer: 2 x k16 steps, 8 warps of 64x32
__device__ __forceinline__ void compute_buf(
    const char* smA, const char* smB,
    int wm, int wn, int gid, int tig, float acc[4][4][4])
{
    #pragma unroll
    for (int ks = 0; ks < 2; ks++) {
        const int kb = (ks * 16 + 2 * tig) * 2;  // byte offset of k-cols
        uint32_t af[4][4];
        #pragma unroll
        for (int mt = 0; mt < 4; mt++) {
            const char* base = smA + (wm + mt * 16 + gid) * ROWB + kb;
            af[mt][0] = *(const uint32_t*)(base);
            af[mt][1] = *(const uint32_t*)(base + 8 * ROWB);
            af[mt][2] = *(const uint32_t*)(base + 16);
            af[mt][3] = *(const uint32_t*)(base + 8 * ROWB + 16);
        }
        uint32_t bf[4][2];
        #pragma unroll
        for (int nt = 0; nt < 4; nt++) {
            const char* bb = smB + (wn + nt * 8 + gid) * ROWB + kb;
            bf[nt][0] = *(const uint32_t*)(bb);
            bf[nt][1] = *(const uint32_t*)(bb + 16);
        }
        #pragma unroll
        for (int mt = 0; mt < 4; mt++)
            #pragma unroll
            for (int nt = 0; nt < 4; nt++)
                MMA_BF16(acc[mt][nt], af[mt], bf[nt]);
    }
}

// 3-stage pipelined NT GEMM mainloop (both operands k-major bf16)
__device__ __forceinline__ void gemm_loop(
    const __nv_bfloat16* Ag, size_t asr,
    const __nv_bfloat16* Bg, size_t bsr,
    int KT, float acc[4][4][4])
{
    extern __shared__ char dsm[];
    const int tid  = threadIdx.x;
    const int wid  = tid >> 5;
    const int lane = tid & 31;
    const int gid  = lane >> 2;
    const int tig  = lane & 3;
    const int wm   = (wid & 1) * 64;
    const int wn   = (wid >> 1) * 32;

    stage_issue(dsm,               Ag, asr, dsm + A_BYTES,               Bg, bsr, 0,  tid);
    stage_issue(dsm + STAGE_B,     Ag, asr, dsm + STAGE_B + A_BYTES,     Bg, bsr, 32, tid);

    for (int i = 0; i < KT; i++) {
        if (i + 2 < KT) CP_WAIT1(); else CP_WAIT0();
        __syncthreads();
        if (i + 2 < KT) {
            char* st = dsm + ((i + 2) % 3) * STAGE_B;
            stage_issue(st, Ag, asr, st + A_BYTES, Bg, bsr, (i + 2) * 32, tid);
        }
        const char* sb = dsm + (i % 3) * STAGE_B;
        compute_buf(sb, sb + A_BYTES, wm, wn, gid, tig, acc);
    }
}

// ---------------------------------------------------------------------------
// conversion kernels
// ---------------------------------------------------------------------------
__global__ void __launch_bounds__(256) convx_kernel(const float* __restrict__ x)
{
    size_t i4 = (size_t)blockIdx.x * blockDim.x + threadIdx.x;  // 2097152 total
    float4 a = ((const float4*)x)[i4];
    __nv_bfloat162 h0 = __floats2bfloat162_rn(a.x, a.y);
    __nv_bfloat162 h1 = __floats2bfloat162_rn(a.z, a.w);
    ((__nv_bfloat162*)g_xb)[i4 * 2]     = h0;
    ((__nv_bfloat162*)g_xb)[i4 * 2 + 1] = h1;
}

__global__ void __launch_bounds__(256) convw_kernel(
    const float* __restrict__ Wq, const float* __restrict__ Wk,
    const float* __restrict__ Wv)
{
    size_t i4 = (size_t)blockIdx.x * blockDim.x + threadIdx.x;  // 196608 total
    int which = (int)(i4 >> 16);
    size_t loc = i4 & 65535;
    const float* src = (which == 0) ? Wq : (which == 1) ? Wk : Wv;
    float4 a = ((const float4*)src)[loc];
    __nv_bfloat162 h0 = __floats2bfloat162_rn(a.x, a.y);
    __nv_bfloat162 h1 = __floats2bfloat162_rn(a.z, a.w);
    ((__nv_bfloat162*)g_wb)[i4 * 2]     = h0;
    ((__nv_bfloat162*)g_wb)[i4 * 2 + 1] = h1;
}

// ---------------------------------------------------------------------------
// Kernel: q/k/v = x @ W^T + b  (bf16 out)
// ---------------------------------------------------------------------------
__global__ void __launch_bounds__(256, 2) qkv_kernel(
    const float* __restrict__ bq, const float* __restrict__ bk,
    const float* __restrict__ bv)
{
    const int which = blockIdx.z;
    const float* bias = (which == 0) ? bq : (which == 1) ? bk : bv;
    __nv_bfloat16* outp = (which == 0) ? g_qb : (which == 1) ? g_kb : g_vb;

    const int m0 = blockIdx.y * 128;
    const int n0 = blockIdx.x * 128;

    float acc[4][4][4] = {};
    gemm_loop(g_xb + (size_t)m0 * NC, NC,
              g_wb + (size_t)which * 512 * 512 + (size_t)n0 * NC, NC,
              NC / 32, acc);

    const int tid = threadIdx.x, wid = tid >> 5, lane = tid & 31;
    const int gid = lane >> 2, tig = lane & 3;
    const int wm = (wid & 1) * 64, wn = (wid >> 1) * 32;

    #pragma unroll
    for (int mt = 0; mt < 4; mt++) {
        #pragma unroll
        for (int nt = 0; nt < 4; nt++) {
            int m = m0 + wm + mt * 16 + gid;
            int n = n0 + wn + nt * 8 + 2 * tig;
            float b0 = bias[n], b1 = bias[n + 1];
            __nv_bfloat162 h0 = __floats2bfloat162_rn(acc[mt][nt][0] + b0, acc[mt][nt][1] + b1);
            __nv_bfloat162 h1 = __floats2bfloat162_rn(acc[mt][nt][2] + b0, acc[mt][nt][3] + b1);
            *(__nv_bfloat162*)(outp + (size_t)m * NK + n) = h0;
            *(__nv_bfloat162*)(outp + (size_t)(m + 8) * NK + n) = h1;
        }
    }
}

// ---------------------------------------------------------------------------
// Kernel: transpose V (bf16) -> g_vT[b*512+n][s]
// tile: 32 s-rows x 64 n-cols
// ---------------------------------------------------------------------------
__global__ void __launch_bounds__(256) vtrans_kernel()
{
    __shared__ __nv_bfloat16 ts[32][66];
    const int b  = blockIdx.z;
    const int n0 = blockIdx.x * 64;
    const int s0 = blockIdx.y * 32;
    const int tid = threadIdx.x;

    // load: 32 rows x 32 uint32 (64 bf16)
    {
        const int cu = tid & 31;        // uint32 col
        const int r0 = tid >> 5;        // 0..7
        #pragma unroll
        for (int j = 0; j < 4; j++) {
            int r = r0 + 8 * j;
            uint32_t v = *(const uint32_t*)(g_vb + ((size_t)(b * NT + s0 + r)) * NK + n0 + cu * 2);
            *(uint32_t*)&ts[r][cu * 2] = v;
        }
    }
    __syncthreads();
    // store transposed: 64 n-rows x 16 uint32 (32 bf16)
    {
        const int cw = tid & 15;        // s-pair index
        const int rn0 = tid >> 4;       // 0..15
        #pragma unroll
        for (int j = 0; j < 4; j++) {
            int n = rn0 + 16 * j;
            __nv_bfloat162 p;
            p.x = ts[2 * cw][n];
            p.y = ts[2 * cw + 1][n];
            *(__nv_bfloat162*)(g_vT + ((size_t)(b * NK + n0 + n)) * NT + s0 + 2 * cw) = p;
        }
    }
}

// ---------------------------------------------------------------------------
// Kernel: S = (q @ k^T) * SCALE, lower-triangle tiles only (fp32 out)
// ---------------------------------------------------------------------------
__global__ void __launch_bounds__(256, 2) scores_kernel()
{
    const int b = blockIdx.y;
    int xi = blockIdx.x;
    int qt = (int)((sqrtf(8.0f * xi + 1.0f) - 1.0f) * 0.5f);
    while ((qt + 1) * (qt + 2) / 2 <= xi) qt++;
    while (qt * (qt + 1) / 2 > xi) qt--;
    const int st = xi - qt * (qt + 1) / 2;

    const int m0 = qt * 128;
    const int n0 = st * 128;

    float acc[4][4][4] = {};
    gemm_loop(g_qb + ((size_t)b * NT + m0) * NK, NK,
              g_kb + ((size_t)b * NT + n0) * NK, NK,
              NK / 32, acc);

    float* S = g_S + (size_t)b * NT * NT;
    const int tid = threadIdx.x, wid = tid >> 5, lane = tid & 31;
    const int gid = lane >> 2, tig = lane & 3;
    const int wm = (wid & 1) * 64, wn = (wid >> 1) * 32;

    #pragma unroll
    for (int mt = 0; mt < 4; mt++) {
        #pragma unroll
        for (int nt = 0; nt < 4; nt++) {
            int m = m0 + wm + mt * 16 + gid;
            int n = n0 + wn + nt * 8 + 2 * tig;
            float2 v0 = { acc[mt][nt][0] * SCALE, acc[mt][nt][1] * SCALE };
            float2 v1 = { acc[mt][nt][2] * SCALE, acc[mt][nt][3] * SCALE };
            *(float2*)(S + (size_t)m * NT + n) = v0;
            *(float2*)(S + (size_t)(m + 8) * NT + n) = v1;
        }
    }
}

// ---------------------------------------------------------------------------
// Kernel: column softmax stats (online) + write P (bf16) into g_P
// ---------------------------------------------------------------------------
__global__ void __launch_bounds__(256) colstats_kernel()
{
    const int b = blockIdx.y;
    const int cc = threadIdx.x & 31;
    const int rl = threadIdx.x >> 5;     // 0..7
    const int col = blockIdx.x * 32 + cc;
    const float* S = g_S + (size_t)b * NT * NT;
    __nv_bfloat16* P = g_P + (size_t)b * NT * NT;

    __shared__ float redm[8][32];
    __shared__ float redz[8][32];

    const int qstart = (col & ~7) + rl;

    float m = -INFINITY, z = 0.f;
    for (int q = qstart; q < NT; q += 8) {
        if (q >= col) {
            float v = S[(size_t)q * NT + col];
            if (v > m) { z = z * __expf(m - v) + 1.f; m = v; }
            else       { z += __expf(v - m); }
        }
    }
    redm[rl][cc] = m;
    redz[rl][cc] = z;
    __syncthreads();
    if (rl == 0) {
        float M = m;
        #pragma unroll
        for (int r = 1; r < 8; r++) M = fmaxf(M, redm[r][cc]);
        float Z = 0.f;
        #pragma unroll
        for (int r = 0; r < 8; r++) Z += redz[r][cc] * __expf(redm[r][cc] - M);
        redm[0][cc] = M;
        redz[0][cc] = 1.f / Z;
    }
    __syncthreads();
    const float cm  = redm[0][cc];
    const float ciz = redz[0][cc];

    // write P over the region attnv reads (from col's 128-block start to NT)
    const int qb = (col & ~127) + rl;
    for (int q = qb; q < NT; q += 8) {
        float p = 0.f;
        if (q >= col)
            p = __expf(S[(size_t)q * NT + col] - cm) * ciz;
        P[(size_t)q * NT + col] = __float2bfloat16(p);
    }
}

// ---------------------------------------------------------------------------
// Kernel: attn = P @ V (B = g_vT), triangular k-range
// ---------------------------------------------------------------------------
__global__ void __launch_bounds__(256, 2) attnv_kernel(float* __restrict__ out)
{
    const int b  = blockIdx.z;
    const int qt = gridDim.y - 1 - blockIdx.y;  // big tiles first
    const int n0 = blockIdx.x * 128;
    const int m0 = qt * 128;
    const int KT = 4 * (qt + 1);

    float acc[4][4][4] = {};
    gemm_loop(g_P  + ((size_t)b * NT + m0) * NT, NT,
              g_vT + ((size_t)b * NK + n0) * NT, NT,
              KT, acc);

    const int tid = threadIdx.x, wid = tid >> 5, lane = tid & 31;
    const int gid = lane >> 2, tig = lane & 3;
    const int wm = (wid & 1) * 64, wn = (wid >> 1) * 32;

    #pragma unroll
    for (int mt = 0; mt < 4; mt++) {
        #pragma unroll
        for (int nt = 0; nt < 4; nt++) {
            int q = m0 + wm + mt * 16 + gid;
            int n = n0 + wn + nt * 8 + 2 * tig;
            float2 v0 = { acc[mt][nt][0], acc[mt][nt][1] };
            float2 v1 = { acc[mt][nt][2], acc[mt][nt][3] };
            *(float2*)(out + ((size_t)b * NT + q) * 1024 + 512 + n) = v0;
            *(float2*)(out + ((size_t)b * NT + q + 8) * 1024 + 512 + n) = v1;
        }
    }
}

// ---------------------------------------------------------------------------
// Kernel: out[..., 0:512] = x
// ---------------------------------------------------------------------------
__global__ void __launch_bounds__(256) copyx_kernel(
    const float* __restrict__ x, float* __restrict__ out)
{
    size_t idx4 = (size_t)blockIdx.x * blockDim.x + threadIdx.x;
    size_t row = idx4 / 128;
    size_t c4  = idx4 % 128;
    ((float4*)out)[row * 256 + c4] = ((const float4*)x)[idx4];
}

// ---------------------------------------------------------------------------
extern "C" void kernel_launch(void* const* d_in, const int* in_sizes, int n_in,
                              void* d_out, int out_size)
{
    const float* x  = (const float*)d_in[0];
    const float* Wq = (const float*)d_in[1];
    const float* bq = (const float*)d_in[2];
    const float* Wk = (const float*)d_in[3];
    const float* bk = (const float*)d_in[4];
    const float* Wv = (const float*)d_in[5];
    const float* bv = (const float*)d_in[6];
    float* out = (float*)d_out;

    const int dsmem = 3 * STAGE_B;  // 61440 B
    cudaFuncSetAttribute(qkv_kernel,    cudaFuncAttributeMaxDynamicSharedMemorySize, dsmem);
    cudaFuncSetAttribute(scores_kernel, cudaFuncAttributeMaxDynamicSharedMemorySize, dsmem);
    cudaFuncSetAttribute(attnv_kernel,  cudaFuncAttributeMaxDynamicSharedMemorySize, dsmem);

    convx_kernel<<<dim3(8192), 256>>>(x);
    convw_kernel<<<dim3(768), 256>>>(Wq, Wk, Wv);
    qkv_kernel<<<dim3(4, 128, 3), 256, dsmem>>>(bq, bk, bv);
    vtrans_kernel<<<dim3(8, 64, 8), 256>>>();
    scores_kernel<<<dim3(136, 8), 256, dsmem>>>();
    colstats_kernel<<<dim3(64, 8), 256>>>();
    attnv_kernel<<<dim3(4, 16, 8), 256, dsmem>>>(out);
    copyx_kernel<<<dim3(8192), 256>>>(x, out);
}